// round 1
// baseline (speedup 1.0000x reference)
#include <cuda_runtime.h>
#include <math.h>

#define NN   50000
#define EE   600000
#define DD   128
#define CC   128
#define GG   64
#define NCLS 10

// ---------------- scratch (static device globals; no allocation) ----------------
__device__ __align__(16) float g_q[NN * CC];
__device__ __align__(16) float g_k[NN * CC];
__device__ __align__(16) float g_v[NN * CC];
__device__ __align__(16) float g_h0[NN * CC];   // layer-0 output (pre-relu)
__device__ __align__(16) float g_h1[NN * CC];   // layer-1 output (pre-relu)
__device__ float g_score[EE];
__device__ float g_m[NN];
__device__ float g_den[NN];
__device__ __align__(16) float g_sums[GG * CC];
__device__ float g_cnt[GG];

// ---------------- helpers ----------------
__device__ __forceinline__ void atomicMaxF(float* addr, float val) {
    int old = __float_as_int(*addr);
    while (__int_as_float(old) < val) {
        int assumed = old;
        old = atomicCAS((int*)addr, assumed, __float_as_int(val));
        if (old == assumed) break;
    }
}

__device__ __forceinline__ void red_add_v4(float* addr, float a, float b, float c, float d) {
    asm volatile("red.global.add.v4.f32 [%0], {%1, %2, %3, %4};"
                 :: "l"(addr), "f"(a), "f"(b), "f"(c), "f"(d) : "memory");
}

// ---------------- init kernels ----------------
__global__ void init_nodes_kernel() {
    int i = blockIdx.x * blockDim.x + threadIdx.x;
    if (i < NN) {
        g_m[i] = -INFINITY;
        g_den[i] = 0.0f;
    }
}

__global__ void init_pool_kernel() {
    int i = blockIdx.x * blockDim.x + threadIdx.x;
    if (i < GG * CC) g_sums[i] = 0.0f;
    if (i < GG) g_cnt[i] = 0.0f;
}

// ---------------- fused 4-way GEMM: y = act(X) @ W + b ----------------
// blockIdx.y selects (Wq->g_q, Wk->g_k, Wv->g_v, Ws->out-layer-buffer).
// X == nullptr means "read g_h0 with relu applied" (layer 1 input).
__global__ __launch_bounds__(256) void gemm4_kernel(
    const float* __restrict__ X,
    const float* __restrict__ Wq, const float* __restrict__ Wk,
    const float* __restrict__ Wv, const float* __restrict__ Ws,
    const float* __restrict__ bq, const float* __restrict__ bk,
    const float* __restrict__ bv, const float* __restrict__ bs,
    int layer)
{
    const float* W; const float* B; float* O;
    switch (blockIdx.y) {
        case 0:  W = Wq; B = bq; O = g_q; break;
        case 1:  W = Wk; B = bk; O = g_k; break;
        case 2:  W = Wv; B = bv; O = g_v; break;
        default: W = Ws; B = bs; O = (layer == 0) ? g_h0 : g_h1; break;
    }
    const bool relu_in = (X == nullptr);
    const float* Xp = relu_in ? g_h0 : X;

    __shared__ float xs[16][129];   // transposed x tile, padded (bank-conflict free stores)
    __shared__ float ws[16][128];

    const int tid = threadIdx.x;
    const int tx = tid & 15;        // col group 0..15 -> cols tx*8..tx*8+7
    const int ty = tid >> 4;        // row group 0..15 -> rows ty*8..ty*8+7
    const int row0 = blockIdx.x * 128;

    float acc[8][8];
    #pragma unroll
    for (int i = 0; i < 8; i++)
        #pragma unroll
        for (int j = 0; j < 8; j++) acc[i][j] = 0.0f;

    for (int k0 = 0; k0 < DD; k0 += 16) {
        // load X tile [128 rows x 16 k], stored transposed
        #pragma unroll
        for (int i = tid; i < 512; i += 256) {
            int r = i >> 2, c4 = i & 3;
            int gr = row0 + r;
            float4 f = make_float4(0.f, 0.f, 0.f, 0.f);
            if (gr < NN)
                f = reinterpret_cast<const float4*>(Xp)[gr * (DD / 4) + (k0 >> 2) + c4];
            if (relu_in) {
                f.x = fmaxf(f.x, 0.f); f.y = fmaxf(f.y, 0.f);
                f.z = fmaxf(f.z, 0.f); f.w = fmaxf(f.w, 0.f);
            }
            xs[c4 * 4 + 0][r] = f.x;
            xs[c4 * 4 + 1][r] = f.y;
            xs[c4 * 4 + 2][r] = f.z;
            xs[c4 * 4 + 3][r] = f.w;
        }
        // load W tile [16 k x 128 cols]
        #pragma unroll
        for (int i = tid; i < 512; i += 256) {
            int r = i >> 5, c4 = i & 31;
            float4 f = reinterpret_cast<const float4*>(W)[(k0 + r) * (CC / 4) + c4];
            reinterpret_cast<float4*>(&ws[r][c4 * 4])[0] = f;
        }
        __syncthreads();

        #pragma unroll
        for (int kk = 0; kk < 16; kk++) {
            float a[8], b[8];
            #pragma unroll
            for (int i = 0; i < 8; i++) a[i] = xs[kk][ty * 8 + i];
            float4 b0 = reinterpret_cast<const float4*>(&ws[kk][tx * 8])[0];
            float4 b1 = reinterpret_cast<const float4*>(&ws[kk][tx * 8])[1];
            b[0] = b0.x; b[1] = b0.y; b[2] = b0.z; b[3] = b0.w;
            b[4] = b1.x; b[5] = b1.y; b[6] = b1.z; b[7] = b1.w;
            #pragma unroll
            for (int i = 0; i < 8; i++)
                #pragma unroll
                for (int j = 0; j < 8; j++)
                    acc[i][j] = fmaf(a[i], b[j], acc[i][j]);
        }
        __syncthreads();
    }

    float bias[8];
    #pragma unroll
    for (int j = 0; j < 8; j++) bias[j] = B[tx * 8 + j];

    #pragma unroll
    for (int i = 0; i < 8; i++) {
        int gr = row0 + ty * 8 + i;
        if (gr < NN) {
            float4 o0 = make_float4(acc[i][0] + bias[0], acc[i][1] + bias[1],
                                    acc[i][2] + bias[2], acc[i][3] + bias[3]);
            float4 o1 = make_float4(acc[i][4] + bias[4], acc[i][5] + bias[5],
                                    acc[i][6] + bias[6], acc[i][7] + bias[7]);
            reinterpret_cast<float4*>(&O[gr * CC + tx * 8])[0] = o0;
            reinterpret_cast<float4*>(&O[gr * CC + tx * 8])[1] = o1;
        }
    }
}

// ---------------- edge pass 1: score + segment max ----------------
__global__ __launch_bounds__(256) void edge_score_kernel(
    const int* __restrict__ src, const int* __restrict__ dst)
{
    int t = blockIdx.x * 256 + threadIdx.x;
    int e = t >> 5;
    int lane = t & 31;
    if (e >= EE) return;
    int s = src[e], d = dst[e];
    float4 qa = reinterpret_cast<const float4*>(g_q)[d * 32 + lane];
    float4 ka = reinterpret_cast<const float4*>(g_k)[s * 32 + lane];
    float dot = qa.x * ka.x + qa.y * ka.y + qa.z * ka.z + qa.w * ka.w;
    #pragma unroll
    for (int o = 16; o > 0; o >>= 1) dot += __shfl_xor_sync(0xffffffffu, dot, o);
    if (lane == 0) {
        float sc = dot * 0.08838834764831843f;   // 1/sqrt(128)
        g_score[e] = sc;
        atomicMaxF(&g_m[d], sc);
    }
}

// ---------------- edge pass 2: exp + denominator ----------------
__global__ __launch_bounds__(256) void edge_exp_kernel(const int* __restrict__ dst)
{
    int e = blockIdx.x * 256 + threadIdx.x;
    if (e >= EE) return;
    int d = dst[e];
    float w = expf(g_score[e] - g_m[d]);
    g_score[e] = w;
    atomicAdd(&g_den[d], w);
}

// ---------------- edge pass 3: alpha * v scatter ----------------
__global__ __launch_bounds__(256) void edge_scatter_kernel(
    const int* __restrict__ src, const int* __restrict__ dst, int layer)
{
    int t = blockIdx.x * 256 + threadIdx.x;
    int e = t >> 5;
    int lane = t & 31;
    if (e >= EE) return;
    int s = src[e], d = dst[e];
    float alpha = g_score[e] / g_den[d];
    float4 vv = reinterpret_cast<const float4*>(g_v)[s * 32 + lane];
    float* O = (layer == 0) ? g_h0 : g_h1;
    red_add_v4(&O[d * CC + lane * 4],
               alpha * vv.x, alpha * vv.y, alpha * vv.z, alpha * vv.w);
}

// ---------------- global mean pool (reads relu(g_h1)) ----------------
__global__ __launch_bounds__(256) void pool_kernel(const int* __restrict__ batch)
{
    int t = blockIdx.x * 256 + threadIdx.x;
    int n = t >> 5;
    int lane = t & 31;
    if (n >= NN) return;
    int g = batch[n];
    float4 h = reinterpret_cast<const float4*>(g_h1)[n * 32 + lane];
    h.x = fmaxf(h.x, 0.f); h.y = fmaxf(h.y, 0.f);
    h.z = fmaxf(h.z, 0.f); h.w = fmaxf(h.w, 0.f);
    red_add_v4(&g_sums[g * CC + lane * 4], h.x, h.y, h.z, h.w);
    if (lane == 0) atomicAdd(&g_cnt[g], 1.0f);
}

// ---------------- classifier + log_softmax ----------------
__global__ void final_kernel(const float* __restrict__ W_fc,
                             const float* __restrict__ b_fc,
                             float* __restrict__ out)
{
    int g = blockIdx.x;
    int j = threadIdx.x;
    __shared__ float sl[12];
    float inv = 1.0f / fmaxf(g_cnt[g], 1.0f);
    if (j < NCLS) {
        float acc = b_fc[j];
        for (int c = 0; c < CC; c++)
            acc += g_sums[g * CC + c] * inv * W_fc[c * NCLS + j];
        sl[j] = acc;
    }
    __syncwarp();
    if (j == 0) {
        float mx = sl[0];
        for (int i = 1; i < NCLS; i++) mx = fmaxf(mx, sl[i]);
        float ssum = 0.f;
        for (int i = 0; i < NCLS; i++) ssum += expf(sl[i] - mx);
        sl[10] = mx + logf(ssum);
    }
    __syncwarp();
    if (j < NCLS) out[g * NCLS + j] = sl[j] - sl[10];
}

// ---------------- launch ----------------
extern "C" void kernel_launch(void* const* d_in, const int* in_sizes, int n_in,
                              void* d_out, int out_size)
{
    const float* x    = (const float*)d_in[0];
    const int*   ei   = (const int*)d_in[1];
    const int*   batch= (const int*)d_in[2];
    const float* Wq   = (const float*)d_in[3];
    const float* bq   = (const float*)d_in[4];
    const float* Wk   = (const float*)d_in[5];
    const float* bk   = (const float*)d_in[6];
    const float* Wv   = (const float*)d_in[7];
    const float* bv   = (const float*)d_in[8];
    const float* Ws   = (const float*)d_in[9];
    const float* bs   = (const float*)d_in[10];
    const float* W_fc = (const float*)d_in[11];
    const float* b_fc = (const float*)d_in[12];
    float* out = (float*)d_out;

    const int* src = ei;
    const int* dst = ei + EE;

    const int gemm_gx   = (NN + 127) / 128;          // 391
    const int edge_gx   = (EE * 32 + 255) / 256;     // 75000
    const int edge1_gx  = (EE + 255) / 256;          // 2344
    const int node_gx   = (NN + 255) / 256;          // 196
    const int pool_gx   = (NN * 32 + 255) / 256;     // 6250

    init_pool_kernel<<<(GG * CC + 255) / 256, 256>>>();

    for (int l = 0; l < 2; l++) {
        init_nodes_kernel<<<node_gx, 256>>>();
        gemm4_kernel<<<dim3(gemm_gx, 4), 256>>>(
            (l == 0) ? x : nullptr,
            Wq + l * DD * CC, Wk + l * DD * CC, Wv + l * DD * CC, Ws + l * DD * CC,
            bq + l * CC, bk + l * CC, bv + l * CC, bs + l * CC,
            l);
        edge_score_kernel<<<edge_gx, 256>>>(src, dst);
        edge_exp_kernel<<<edge1_gx, 256>>>(dst);
        edge_scatter_kernel<<<edge_gx, 256>>>(src, dst, l);
    }

    pool_kernel<<<pool_gx, 256>>>(batch);
    final_kernel<<<GG, 32>>>(W_fc, b_fc, out);
}